// round 5
// baseline (speedup 1.0000x reference)
#include <cuda_runtime.h>
#include <cuda_fp16.h>
#include <cstdint>

#define N_NODES    2048
#define FDIM       256
#define HID        64
#define TEMPLATE_N 10
#define TRIG_ELEMS (N_NODES * FDIM)
#define EW1B_OFF   (FDIM * HID)

// device scratch
__device__ float g_h3[FDIM];
__device__ float g_base[HID];            // h3@(w1a+w1b) + eb1
__device__ float g_npa[N_NODES * HID];   // 0.1*noise@w1a (rows 0..9 zero)
__device__ float g_npb[N_NODES * HID];   // 0.1*noise@w1b (rows 0..9 zero)

// ---- f32x2 helpers (prep GEMM only) --------------------------------------
__device__ __forceinline__ unsigned long long f2_fma(unsigned long long a, unsigned long long b, unsigned long long c) {
    unsigned long long r; asm("fma.rn.f32x2 %0, %1, %2, %3;" : "=l"(r) : "l"(a), "l"(b), "l"(c)); return r;
}
__device__ __forceinline__ void f2_unpack(float& lo, float& hi, unsigned long long v) {
    asm("mov.b64 {%0, %1}, %2;" : "=f"(lo), "=f"(hi) : "l"(v));
}
__device__ __forceinline__ unsigned long long f2_pack(float lo, float hi) {
    unsigned long long r; asm("mov.b64 %0, {%1, %2};" : "=l"(r) : "f"(lo), "f"(hi)); return r;
}

// ---------------------------------------------------------------------------
// Kernel P: 257 blocks x 256 threads.
//   block 0   : MLP -> g_h3, g_base
//   blocks 1+ : noise GEMM, 8 rows/block; 2-way k split per thread
//               (c = tid&127 column, kh = tid>>7 k-half, all 8 rows/thread)
// ---------------------------------------------------------------------------
#define KP_ROWS   8
#define NS_STRIDE 12   // 8 + pad; k*12 floats -> 16B aligned

__global__ void __launch_bounds__(256, 3)
kP_prep(const float* __restrict__ cf, const int* __restrict__ sel,
        const float* __restrict__ w1, const float* __restrict__ b1,
        const float* __restrict__ w2, const float* __restrict__ b2,
        const float* __restrict__ w3, const float* __restrict__ b3,
        const float* __restrict__ ew1, const float* __restrict__ eb1,
        const float* __restrict__ noise)
{
    __shared__ float sBuf[4096];   // 16 KB: nS (3072) then reduction scratch
    const int tid = threadIdx.x;

    if (blockIdx.x == 0) {
        // ---------------- MLP ----------------
        float* proto = sBuf;
        float* h1    = sBuf + 256;
        float* h2    = sBuf + 320;
        float* h3S   = sBuf + 384;
        float* part  = sBuf + 640;

        {
            float s = 0.f;
            #pragma unroll
            for (int r = 0; r < TEMPLATE_N; ++r)
                s += cf[(size_t)sel[r] * FDIM + tid];
            proto[tid] = s * (1.0f / TEMPLATE_N);
        }
        __syncthreads();

        {
            const int c = tid & 63, q = tid >> 6, k0 = q * 64;
            float acc = 0.f;
            #pragma unroll 8
            for (int k = 0; k < 64; ++k)
                acc = fmaf(proto[k0 + k], w1[(k0 + k) * HID + c], acc);
            part[tid] = acc;
        }
        __syncthreads();
        if (tid < HID)
            h1[tid] = fmaxf(part[tid] + part[64 + tid] + part[128 + tid] + part[192 + tid] + b1[tid], 0.f);
        __syncthreads();

        {
            const int c = tid & 63, q = tid >> 6, k0 = q * 16;
            float acc = 0.f;
            #pragma unroll
            for (int k = 0; k < 16; ++k)
                acc = fmaf(h1[k0 + k], w2[(k0 + k) * HID + c], acc);
            part[tid] = acc;
        }
        __syncthreads();
        if (tid < HID)
            h2[tid] = fmaxf(part[tid] + part[64 + tid] + part[128 + tid] + part[192 + tid] + b2[tid], 0.f);
        __syncthreads();

        {
            float acc = b3[tid];
            #pragma unroll 8
            for (int k = 0; k < HID; ++k)
                acc = fmaf(h2[k], w3[k * FDIM + tid], acc);
            float v = __fdividef(1.0f, 1.0f + __expf(-acc));
            g_h3[tid] = v;
            h3S[tid]  = v;
        }
        __syncthreads();

        {
            const int c = tid & 63, q = tid >> 6, k0 = q * 64;
            float acc = 0.f;
            #pragma unroll 4
            for (int k = 0; k < 64; ++k) {
                float w = ew1[(k0 + k) * HID + c] + ew1[EW1B_OFF + (k0 + k) * HID + c];
                acc = fmaf(h3S[k0 + k], w, acc);
            }
            part[tid] = acc;
        }
        __syncthreads();
        if (tid < HID)
            g_base[tid] = part[tid] + part[64 + tid] + part[128 + tid] + part[192 + tid] + eb1[tid];
        return;
    }

    // ---------------- noise GEMM (blocks 1..256), 8 rows each ----------------
    float* nS = sBuf;                       // [FDIM][NS_STRIDE] k-major
    const int r0 = (blockIdx.x - 1) * KP_ROWS;

    #pragma unroll
    for (int u = 0; u < KP_ROWS; ++u) {
        const int r = r0 + u;
        float v = 0.f;
        if (r >= TEMPLATE_N)
            v = 0.1f * noise[(size_t)(r - TEMPLATE_N) * FDIM + tid];
        nS[tid * NS_STRIDE + u] = v;
    }
    __syncthreads();

    const int c  = tid & 127;               // column (pa if <64, else pb)
    const int kh = tid >> 7;                // k half
    const bool is_pa = (c < HID);
    const float* wcol = ew1 + (is_pa ? c : (EW1B_OFF + (c - HID))) + kh * 128 * HID;
    const float* nSk  = nS + kh * 128 * NS_STRIDE;

    unsigned long long acc0 = f2_pack(0.f, 0.f), acc1 = acc0, acc2 = acc0, acc3 = acc0;

    #pragma unroll 4
    for (int k = 0; k < 128; ++k) {
        const float w = wcol[k * HID];
        const unsigned long long wp = f2_pack(w, w);
        const float* row = nSk + k * NS_STRIDE;
        const ulonglong2 A = *reinterpret_cast<const ulonglong2*>(row);      // rows 0-3
        const ulonglong2 B = *reinterpret_cast<const ulonglong2*>(row + 4);  // rows 4-7
        acc0 = f2_fma(A.x, wp, acc0);
        acc1 = f2_fma(A.y, wp, acc1);
        acc2 = f2_fma(B.x, wp, acc2);
        acc3 = f2_fma(B.y, wp, acc3);
    }
    __syncthreads();   // nS no longer needed; reuse sBuf as reduction scratch

    // stash kh=1 partials, then kh=0 combines and writes.
    float p[8];
    f2_unpack(p[0], p[1], acc0);
    f2_unpack(p[2], p[3], acc1);
    f2_unpack(p[4], p[5], acc2);
    f2_unpack(p[6], p[7], acc3);

    if (kh == 1) {
        #pragma unroll
        for (int u = 0; u < 8; ++u) sBuf[c * 8 + u] = p[u];
    }
    __syncthreads();
    if (kh == 0) {
        float* dst = (is_pa ? g_npa : g_npb);
        const int cc = is_pa ? c : (c - HID);
        #pragma unroll
        for (int u = 0; u < 8; ++u)
            dst[(r0 + u) * HID + cc] = p[u] + sBuf[c * 8 + u];
    }
}

// ---------------------------------------------------------------------------
// Kernel E: 288 tiles (256 j x 32 i), 256 threads, 3 CTAs/SM.
//   w2 lives in SHARED (uniform -> LDS broadcast), pb per-thread regs.
// ---------------------------------------------------------------------------
#define TI 32
#define TJ 256
#define N_TILES 288     // sum over jt of (8*jt + 8)

__global__ void __launch_bounds__(TJ, 3)
kE_edges(const float* __restrict__ noise,
         const float* __restrict__ ew2,
         const float* __restrict__ eb2,
         float* __restrict__ out_trig,
         float* __restrict__ out_edge)
{
    __shared__ __half2 paS[TI * 32];          // 4 KB
    __shared__ __half2 w2S[32];               // 128 B
    const int tid = threadIdx.x;

    // ---- stage 0: trig rows ----
    {
        const float h3v = g_h3[tid];
        for (int r = blockIdx.x; r < N_NODES; r += N_TILES) {
            float v = h3v;
            if (r >= TEMPLATE_N)
                v = fmaf(0.1f, noise[(size_t)(r - TEMPLATE_N) * FDIM + tid], v);
            out_trig[(size_t)r * FDIM + tid] = v;
        }
    }

    // ---- tile mapping ----
    int rem = blockIdx.x, jt;
    for (jt = 0; jt < 8; ++jt) { const int n = 8 * jt + 8; if (rem < n) break; rem -= n; }
    const int it = rem;
    const int j0 = jt * TJ;
    const int i0 = it * TI;

    // ---- stage 1a: pa tile -> fp16 smem; w2 -> fp16 smem ----
    for (int idx = tid; idx < TI * 32; idx += TJ) {
        const int ii = idx >> 5, kp = idx & 31;
        const float lo = g_npa[(i0 + ii) * HID + 2 * kp]     + g_base[2 * kp];
        const float hi = g_npa[(i0 + ii) * HID + 2 * kp + 1] + g_base[2 * kp + 1];
        paS[idx] = __floats2half2_rn(lo, hi);
    }
    if (tid < 16) {
        const float4 w = __ldg(reinterpret_cast<const float4*>(ew2) + tid);
        w2S[2 * tid]     = __floats2half2_rn(w.x, w.y);
        w2S[2 * tid + 1] = __floats2half2_rn(w.z, w.w);
    }

    // ---- stage 1b: pb row -> fp16 regs ----
    const int j = j0 + tid;
    __half2 pb2[32];
    {
        const float4* pbp = reinterpret_cast<const float4*>(g_npb + j * HID);
        #pragma unroll
        for (int q = 0; q < 16; ++q) {
            float4 v = pbp[q];
            pb2[2 * q]     = __floats2half2_rn(v.x, v.y);
            pb2[2 * q + 1] = __floats2half2_rn(v.z, v.w);
        }
    }
    const float ebb = eb2[0];
    const __half2 one2 = __floats2half2_rn(1.0f, 1.0f);
    __syncthreads();

    // ---- stage 2: pair loop, 2 i's per iteration, 8 acc chains ----
    const uint4* paS4 = reinterpret_cast<const uint4*>(paS);
    const uint4* w2S4 = reinterpret_cast<const uint4*>(w2S);

    #pragma unroll 2
    for (int ii = 0; ii < TI; ii += 2) {
        __half2 a0 = __float2half2_rn(0.f), a1 = a0, a2 = a0, a3 = a0;
        __half2 b0 = a0, b1 = a0, b2v = a0, b3v = a0;

        #pragma unroll
        for (int q = 0; q < 8; ++q) {
            const uint4 PA = paS4[ii * 8 + q];
            const uint4 PB = paS4[(ii + 1) * 8 + q];
            const uint4 W  = w2S4[q];                       // uniform broadcast
            const __half2 w0 = *reinterpret_cast<const __half2*>(&W.x);
            const __half2 w1v = *reinterpret_cast<const __half2*>(&W.y);
            const __half2 w2v = *reinterpret_cast<const __half2*>(&W.z);
            const __half2 w3v = *reinterpret_cast<const __half2*>(&W.w);
            const int kp = q * 4;
            __half2 h;
            h = __hfma2_relu(*reinterpret_cast<const __half2*>(&PA.x), one2, pb2[kp + 0]); a0 = __hfma2(h, w0, a0);
            h = __hfma2_relu(*reinterpret_cast<const __half2*>(&PA.y), one2, pb2[kp + 1]); a1 = __hfma2(h, w1v, a1);
            h = __hfma2_relu(*reinterpret_cast<const __half2*>(&PA.z), one2, pb2[kp + 2]); a2 = __hfma2(h, w2v, a2);
            h = __hfma2_relu(*reinterpret_cast<const __half2*>(&PA.w), one2, pb2[kp + 3]); a3 = __hfma2(h, w3v, a3);
            h = __hfma2_relu(*reinterpret_cast<const __half2*>(&PB.x), one2, pb2[kp + 0]); b0  = __hfma2(h, w0, b0);
            h = __hfma2_relu(*reinterpret_cast<const __half2*>(&PB.y), one2, pb2[kp + 1]); b1  = __hfma2(h, w1v, b1);
            h = __hfma2_relu(*reinterpret_cast<const __half2*>(&PB.z), one2, pb2[kp + 2]); b2v = __hfma2(h, w2v, b2v);
            h = __hfma2_relu(*reinterpret_cast<const __half2*>(&PB.w), one2, pb2[kp + 3]); b3v = __hfma2(h, w3v, b3v);
        }

        {
            const int i = i0 + ii;
            if (j > i) {
                const __half2 st = __hadd2(__hadd2(a0, a1), __hadd2(a2, a3));
                const float2 f = __half22float2(st);
                const float s = f.x + f.y + ebb;
                const float pr = __fdividef(1.0f, 1.0f + __expf(-s));
                const int base = i * (2 * N_NODES - i - 1) / 2;
                out_edge[base + (j - i - 1)] = pr;
            }
        }
        {
            const int i = i0 + ii + 1;
            if (j > i) {
                const __half2 st = __hadd2(__hadd2(b0, b1), __hadd2(b2v, b3v));
                const float2 f = __half22float2(st);
                const float s = f.x + f.y + ebb;
                const float pr = __fdividef(1.0f, 1.0f + __expf(-s));
                const int base = i * (2 * N_NODES - i - 1) / 2;
                out_edge[base + (j - i - 1)] = pr;
            }
        }
    }
}

// ---------------------------------------------------------------------------
extern "C" void kernel_launch(void* const* d_in, const int* in_sizes, int n_in,
                              void* d_out, int out_size)
{
    const float* cf    = (const float*)d_in[0];
    const int*   sel   = (const int*)  d_in[1];
    const float* noise = (const float*)d_in[2];
    const float* g1w   = (const float*)d_in[3];
    const float* g1b   = (const float*)d_in[4];
    const float* g2w   = (const float*)d_in[5];
    const float* g2b   = (const float*)d_in[6];
    const float* g3w   = (const float*)d_in[7];
    const float* g3b   = (const float*)d_in[8];
    const float* ew1   = (const float*)d_in[9];
    const float* eb1   = (const float*)d_in[10];
    const float* ew2   = (const float*)d_in[11];
    const float* eb2   = (const float*)d_in[12];

    float* out      = (float*)d_out;
    float* out_trig = out;
    float* out_edge = out + TRIG_ELEMS;

    kP_prep<<<257, 256>>>(cf, sel, g1w, g1b, g2w, g2b, g3w, g3b, ew1, eb1, noise);
    kE_edges<<<N_TILES, TJ>>>(noise, ew2, eb2, out_trig, out_edge);
}